// round 16
// baseline (speedup 1.0000x reference)
#include <cuda_runtime.h>
#include <cuda_fp16.h>
#include <math.h>
#include <float.h>
#include <stdint.h>

#define BB 16
#define NS 4096
#define NQ 4096
#define DD 512
#define CC 128
#define QTILE 64
#define GEMM_BLOCKS (BB * (NQ / QTILE))   // 1024
#define MARGIN 0.25f

// ---------------- static device scratch (no runtime alloc) ----------------
__device__ __half g_proto_h[(size_t)BB * CC * DD];            // [b][c][d] fp16
__device__ float  g_proto_f[(size_t)BB * CC * DD];            // [b][c][d] fp32
__device__ float  g_psq[BB * CC];
__device__ float  g_loss_part[GEMM_BLOCKS];
__device__ int    g_corr_part[GEMM_BLOCKS];
__device__ unsigned int g_done = 0;       // self-resetting completion counter

// ---------------- helpers ----------------
__device__ __forceinline__ uint32_t smem_u32(const void* p) {
    uint32_t a;
    asm("{ .reg .u64 t; cvta.to.shared.u64 t, %1; cvt.u32.u64 %0, t; }" : "=r"(a) : "l"(p));
    return a;
}
__device__ __forceinline__ void cp_async16(uint32_t dst, const void* src) {
    asm volatile("cp.async.cg.shared.global [%0], [%1], 16;" :: "r"(dst), "l"(src));
}
__device__ __forceinline__ void cp_commit() {
    asm volatile("cp.async.commit_group;" ::: "memory");
}
__device__ __forceinline__ void cp_wait0() {
    asm volatile("cp.async.wait_group 0;" ::: "memory");
}
__device__ __forceinline__ void ldsm4(uint32_t* r, uint32_t addr) {
    asm volatile("ldmatrix.sync.aligned.m8n8.x4.shared.b16 {%0,%1,%2,%3}, [%4];"
                 : "=r"(r[0]), "=r"(r[1]), "=r"(r[2]), "=r"(r[3]) : "r"(addr));
}
__device__ __forceinline__ void mma_f16(float* c, const uint32_t* a,
                                        uint32_t b0, uint32_t b1) {
    asm volatile("mma.sync.aligned.m16n8k16.row.col.f32.f16.f16.f32 "
                 "{%0,%1,%2,%3}, {%4,%5,%6,%7}, {%8,%9}, {%0,%1,%2,%3};"
                 : "+f"(c[0]), "+f"(c[1]), "+f"(c[2]), "+f"(c[3])
                 : "r"(a[0]), "r"(a[1]), "r"(a[2]), "r"(a[3]), "r"(b0), "r"(b1));
}
__device__ __forceinline__ uint32_t pkhf(float a, float b) {
    __half2 t = __floats2half2_rn(a, b);
    return *reinterpret_cast<uint32_t*>(&t);
}

// ---------------------------------------------------------------------------
// Kernel 1: fused stable-compaction + gather-sum prototypes.
// Grid (128 c, 16 b), 256 threads (thread = 2 d-lanes; handles 16 targets).
// Phase A: count+scan+compact sample ids of class c (order-preserving).
// Phase B: contiguous coalesced float2 gather-sum, 8 independent chains
//   (fixed order -> deterministic). Emits fp16+fp32 protos + p_sq.
// ---------------------------------------------------------------------------
__global__ void psum_kernel(const float* __restrict__ sup,
                            const int* __restrict__ stgt) {
    __shared__ int   sidx[NS];        // 16 KB
    __shared__ int   scanbuf[256];
    __shared__ float red[256];
    const int c = blockIdx.x, b = blockIdx.y, d = threadIdx.x;

    // ---- Phase A ----
    int t16[16];
    {
        const int4* tg = (const int4*)(stgt + (size_t)b * NS + d * 16);
        *(int4*)(t16)      = tg[0];
        *(int4*)(t16 + 4)  = tg[1];
        *(int4*)(t16 + 8)  = tg[2];
        *(int4*)(t16 + 12) = tg[3];
    }
    int cnt = 0;
    #pragma unroll
    for (int u = 0; u < 16; u++) cnt += (t16[u] == c);
    scanbuf[d] = cnt;
    __syncthreads();
    for (int off = 1; off < 256; off <<= 1) {
        int v = (d >= off) ? scanbuf[d - off] : 0;
        __syncthreads();
        scanbuf[d] += v;
        __syncthreads();
    }
    int w = scanbuf[d] - cnt;
    const int total = scanbuf[255];
    #pragma unroll
    for (int u = 0; u < 16; u++)
        if (t16[u] == c) sidx[w++] = d * 16 + u;
    __syncthreads();

    // ---- Phase B: float2 gather-sum, 8 chains ----
    const float2* supb = (const float2*)(sup + (size_t)b * NS * DD + d * 2);
    float2 s0 = {0.f, 0.f}, s1 = {0.f, 0.f}, s2 = {0.f, 0.f}, s3 = {0.f, 0.f};
    float2 s4 = {0.f, 0.f}, s5 = {0.f, 0.f}, s6 = {0.f, 0.f}, s7 = {0.f, 0.f};
    const size_t RS = DD / 2;       // float2 row stride
    int kk = 0;
    for (; kk + 8 <= total; kk += 8) {
        float2 v0 = supb[(size_t)sidx[kk + 0] * RS];
        float2 v1 = supb[(size_t)sidx[kk + 1] * RS];
        float2 v2 = supb[(size_t)sidx[kk + 2] * RS];
        float2 v3 = supb[(size_t)sidx[kk + 3] * RS];
        float2 v4 = supb[(size_t)sidx[kk + 4] * RS];
        float2 v5 = supb[(size_t)sidx[kk + 5] * RS];
        float2 v6 = supb[(size_t)sidx[kk + 6] * RS];
        float2 v7 = supb[(size_t)sidx[kk + 7] * RS];
        s0.x += v0.x; s0.y += v0.y;  s1.x += v1.x; s1.y += v1.y;
        s2.x += v2.x; s2.y += v2.y;  s3.x += v3.x; s3.y += v3.y;
        s4.x += v4.x; s4.y += v4.y;  s5.x += v5.x; s5.y += v5.y;
        s6.x += v6.x; s6.y += v6.y;  s7.x += v7.x; s7.y += v7.y;
    }
    for (; kk < total; kk++) {
        float2 v = supb[(size_t)sidx[kk] * RS];
        s0.x += v.x; s0.y += v.y;
    }

    const float inv = 1.0f / fmaxf((float)total, 1.0f);
    const float m0 = (((s0.x + s1.x) + (s2.x + s3.x)) + ((s4.x + s5.x) + (s6.x + s7.x))) * inv;
    const float m1 = (((s0.y + s1.y) + (s2.y + s3.y)) + ((s4.y + s5.y) + (s6.y + s7.y))) * inv;

    const size_t o = ((size_t)b * CC + c) * DD + d * 2;
    *(float2*)(g_proto_f + o) = make_float2(m0, m1);
    *(__half2*)(g_proto_h + o) = __floats2half2_rn(m0, m1);

    red[d] = m0 * m0 + m1 * m1;
    __syncthreads();
    for (int st = 128; st > 0; st >>= 1) {
        if (d < st) red[d] += red[d + st];
        __syncthreads();
    }
    if (d == 0) g_psq[b * CC + c] = red[0];
}

// ---------------------------------------------------------------------------
// Kernel 2: single-pass fp16 mma.sync distance GEMM (128c x 64q tiles),
// pipelined staging, fused argmin / per-query warp refinement / softmax-CE,
// and fused final reduction (threadfence pattern; last block finishes).
// Grid (64 qtiles, 16 b), 256 threads, 3 CTA/SM.
// ---------------------------------------------------------------------------
#define OFF_RMIN  33792
#define OFF_RARG  34816
#define OFF_RSUM  35840
#define OFF_GMIN  36864
#define OFF_GARG  37120
#define SMEM_GEMM 49152

__global__ __launch_bounds__(256, 3)
void gemm_kernel(const float* __restrict__ qry,
                 const int* __restrict__ qtgt,
                 float* __restrict__ pred_out,
                 float* __restrict__ out, int out_size) {
    extern __shared__ char smem[];
    const uint32_t smb = smem_u32(smem);
    float* dist   = (float*)smem;                 // [128 c][66]
    float* redmin = (float*)(smem + OFF_RMIN);    // [4][64] (also final reduce)
    int*   redarg = (int*)  (smem + OFF_RARG);
    float* redsum = (float*)(smem + OFF_RSUM);
    float* gmin   = (float*)(smem + OFF_GMIN);    // [64]
    int*   garg   = (int*)  (smem + OFF_GARG);

    const int tid = threadIdx.x, wid = tid >> 5, lane = tid & 31;
    const int mw = wid & 3, nw = wid >> 2;
    const int qt = blockIdx.x, b = blockIdx.y, q0 = qt * QTILE;

    const float* Qb = qry + ((size_t)b * NQ + q0) * DD;
    const __half* Ah = g_proto_h + (size_t)b * CC * DD;

    float acc[2][4][4];
    #pragma unroll
    for (int i = 0; i < 2; i++)
        #pragma unroll
        for (int j = 0; j < 4; j++)
            #pragma unroll
            for (int k = 0; k < 4; k++) acc[i][j][k] = 0.0f;

    const uint32_t rowTerm = (uint32_t)(lane & 15) << 7;
    const uint32_t sel16   = (uint32_t)(lane & 16);
    const uint32_t laneXor = (uint32_t)(lane & 7) << 4;

    // ---- prologue: stage chunk 0 into buffer 0 ----
    {
        #pragma unroll
        for (int p = 0; p < 4; p++) {
            int idx = p * 256 + tid;
            int row = idx >> 3, c16 = idx & 7;
            uint32_t sw = (uint32_t)(row * 128 + c16 * 16) ^ ((uint32_t)(row & 7) << 4);
            cp_async16(smb + 0 + sw, Ah + (size_t)row * DD + c16 * 8);
        }
        cp_commit();
        #pragma unroll
        for (int p = 0; p < 2; p++) {
            int idx = p * 256 + tid;
            int row = idx >> 3, c16 = idx & 7;
            const float* src = Qb + (size_t)row * DD + c16 * 8;
            float4 v0 = *(const float4*)(src);
            float4 v1 = *(const float4*)(src + 4);
            uint32_t sw = (uint32_t)(row * 128 + c16 * 16) ^ ((uint32_t)(row & 7) << 4);
            *(uint4*)(smem + 32768 + sw) =
                make_uint4(pkhf(v0.x, v0.y), pkhf(v0.z, v0.w), pkhf(v1.x, v1.y), pkhf(v1.z, v1.w));
        }
        cp_wait0();
        __syncthreads();
    }

    for (int ck = 0; ck < 8; ck++) {
        const int cur = ck & 1;
        float4 bv0[2], bv1[2];
        if (ck < 7) {
            const int k0 = (ck + 1) * 64;
            const uint32_t aBuf = (cur ^ 1) * 16384u;
            #pragma unroll
            for (int p = 0; p < 4; p++) {
                int idx = p * 256 + tid;
                int row = idx >> 3, c16 = idx & 7;
                uint32_t sw = (uint32_t)(row * 128 + c16 * 16) ^ ((uint32_t)(row & 7) << 4);
                cp_async16(smb + aBuf + sw, Ah + (size_t)row * DD + k0 + c16 * 8);
            }
            cp_commit();
            #pragma unroll
            for (int p = 0; p < 2; p++) {
                int idx = p * 256 + tid;
                int row = idx >> 3, c16 = idx & 7;
                const float* src = Qb + (size_t)row * DD + k0 + c16 * 8;
                bv0[p] = *(const float4*)(src);
                bv1[p] = *(const float4*)(src + 4);
            }
        }

        // ---- compute current buffer ----
        {
            const uint32_t aT = smb + cur * 16384u;
            const uint32_t bT = smb + 32768u + cur * 8192u;
            #pragma unroll
            for (int ks = 0; ks < 4; ks++) {
                const uint32_t kb = ((uint32_t)(ks * 32) | sel16) ^ laneXor;
                uint32_t afr[2][4], bfr[2][4];
                #pragma unroll
                for (int mt = 0; mt < 2; mt++)
                    ldsm4(afr[mt], aT + ((uint32_t)(mw * 32 + mt * 16) << 7) + rowTerm + kb);
                #pragma unroll
                for (int g = 0; g < 2; g++)
                    ldsm4(bfr[g], bT + ((uint32_t)(nw * 32 + g * 16) << 7) + rowTerm + kb);
                #pragma unroll
                for (int mt = 0; mt < 2; mt++)
                    #pragma unroll
                    for (int g = 0; g < 2; g++) {
                        mma_f16(acc[mt][2 * g + 0], afr[mt], bfr[g][0], bfr[g][2]);
                        mma_f16(acc[mt][2 * g + 1], afr[mt], bfr[g][1], bfr[g][3]);
                    }
            }
        }

        if (ck < 7) {
            const uint32_t bBuf = 32768u + (cur ^ 1) * 8192u;
            #pragma unroll
            for (int p = 0; p < 2; p++) {
                int idx = p * 256 + tid;
                int row = idx >> 3, c16 = idx & 7;
                uint32_t sw = (uint32_t)(row * 128 + c16 * 16) ^ ((uint32_t)(row & 7) << 4);
                *(uint4*)(smem + bBuf + sw) =
                    make_uint4(pkhf(bv0[p].x, bv0[p].y), pkhf(bv0[p].z, bv0[p].w),
                               pkhf(bv1[p].x, bv1[p].y), pkhf(bv1[p].z, bv1[p].w));
            }
            cp_wait0();
        }
        __syncthreads();
    }

    // ---- dist = p_sq - 2*cross (q_sq cancels) ----
    #pragma unroll
    for (int mt = 0; mt < 2; mt++) {
        int cA = mw * 32 + mt * 16 + (lane >> 2);
        float psA = g_psq[b * CC + cA];
        float psB = g_psq[b * CC + cA + 8];
        #pragma unroll
        for (int nt = 0; nt < 4; nt++) {
            int q = nw * 32 + nt * 8 + 2 * (lane & 3);
            float* d0 = &dist[cA * 66 + q];
            float* d1 = &dist[(cA + 8) * 66 + q];
            d0[0] = psA - 2.0f * acc[mt][nt][0];
            d0[1] = psA - 2.0f * acc[mt][nt][1];
            d1[0] = psB - 2.0f * acc[mt][nt][2];
            d1[1] = psB - 2.0f * acc[mt][nt][3];
        }
    }
    __syncthreads();

    // ---- pass 1: per-quarter min -> global approx min ----
    const int q = tid & 63, qr = tid >> 6, c0 = qr * 32;
    {
        float mn = FLT_MAX; int am = 0;
        #pragma unroll 8
        for (int c = 0; c < 32; c++) {
            float v = dist[(c0 + c) * 66 + q];
            if (v < mn) { mn = v; am = c0 + c; }
        }
        redmin[qr * 64 + q] = mn;
        redarg[qr * 64 + q] = am;
    }
    __syncthreads();
    if (tid < QTILE) {
        float g = FLT_MAX; int ga = 0;
        #pragma unroll
        for (int i = 0; i < 4; i++) {
            float v = redmin[i * 64 + tid];
            if (v < g) { g = v; ga = redarg[i * 64 + tid]; }
        }
        gmin[tid] = g; garg[tid] = ga;
    }
    __syncthreads();

    // ---- per-query warp refinement (ballot-scan, no lists/atomics) ----
    for (int qq = wid; qq < QTILE; qq += 8) {
        const float gthr = gmin[qq] + MARGIN;
        uint32_t masks[4]; int cnt = 0;
        #pragma unroll
        for (int k = 0; k < 4; k++) {
            bool cand = dist[(k * 32 + lane) * 66 + qq] < gthr;
            masks[k] = __ballot_sync(0xFFFFFFFFu, cand);
            cnt += __popc(masks[k]);
        }
        if (cnt < 2) continue;
        float4 qv[4];
        const float4* Q4 = (const float4*)(Qb + (size_t)qq * DD);
        #pragma unroll
        for (int j = 0; j < 4; j++) qv[j] = Q4[lane + j * 32];
        #pragma unroll
        for (int k = 0; k < 4; k++) {
            uint32_t m = masks[k];
            while (m) {
                int c = k * 32 + (__ffs(m) - 1);
                m &= m - 1;
                const float4* P = (const float4*)(g_proto_f + ((size_t)b * CC + c) * DD);
                float s = 0.0f;
                #pragma unroll
                for (int j = 0; j < 4; j++) {
                    float4 a = P[lane + j * 32];
                    s = fmaf(a.x, qv[j].x, s);
                    s = fmaf(a.y, qv[j].y, s);
                    s = fmaf(a.z, qv[j].z, s);
                    s = fmaf(a.w, qv[j].w, s);
                }
                #pragma unroll
                for (int o = 16; o > 0; o >>= 1)
                    s += __shfl_xor_sync(0xFFFFFFFFu, s, o);
                if (lane == 0)
                    dist[c * 66 + qq] = g_psq[b * CC + c] - 2.0f * s;
            }
        }
    }
    __syncthreads();

    // ---- final argmin on refined dist ----
    {
        float mn = FLT_MAX; int am = 0;
        #pragma unroll 8
        for (int c = 0; c < 32; c++) {
            float v = dist[(c0 + c) * 66 + q];
            if (v < mn) { mn = v; am = c0 + c; }
        }
        redmin[qr * 64 + q] = mn;
        redarg[qr * 64 + q] = am;
    }
    __syncthreads();
    if (tid < QTILE) {
        float g = FLT_MAX; int ga = 0;
        #pragma unroll
        for (int i = 0; i < 4; i++) {
            float v = redmin[i * 64 + tid];
            if (v < g) { g = v; ga = redarg[i * 64 + tid]; }
        }
        gmin[tid] = g; garg[tid] = ga;
    }
    __syncthreads();

    // ---- softmax-CE: __expf intrinsic ----
    {
        float g = gmin[q];
        float s = 0.0f;
        #pragma unroll 8
        for (int c = 0; c < 32; c++)
            s += __expf(g - dist[(c0 + c) * 66 + q]);
        redsum[qr * 64 + q] = s;
    }
    __syncthreads();

    if (tid < QTILE) {
        float S = redsum[tid] + redsum[64 + tid] + redsum[128 + tid] + redsum[192 + tid];
        int tgt = qtgt[(size_t)b * NQ + q0 + tid];
        float tl = dist[tgt * 66 + tid];
        float nll = tl - gmin[tid] + logf(S);
        int corr = (garg[tid] == tgt);
        if (pred_out) pred_out[(size_t)b * NQ + q0 + tid] = (float)garg[tid];
        redmin[tid] = nll;
        redarg[tid] = corr;
    }
    __syncthreads();
    for (int s2 = 32; s2 > 0; s2 >>= 1) {
        if (tid < s2) { redmin[tid] += redmin[tid + s2]; redarg[tid] += redarg[tid + s2]; }
        __syncthreads();
    }

    // ---- publish partial + last-block fused finalize ----
    __shared__ int slast;
    if (tid == 0) {
        g_loss_part[b * (NQ / QTILE) + qt] = redmin[0];
        g_corr_part[b * (NQ / QTILE) + qt] = redarg[0];
        __threadfence();
        unsigned int old = atomicAdd(&g_done, 1u);
        slast = (old == (unsigned int)(GEMM_BLOCKS - 1));
    }
    __syncthreads();
    if (slast) {
        float ls = 0.0f; int cs = 0;
        #pragma unroll
        for (int i = 0; i < GEMM_BLOCKS / 256; i++) {
            ls += g_loss_part[i * 256 + tid];
            cs += g_corr_part[i * 256 + tid];
        }
        redmin[tid] = ls;
        redarg[tid] = cs;
        __syncthreads();
        for (int s2 = 128; s2 > 0; s2 >>= 1) {
            if (tid < s2) { redmin[tid] += redmin[tid + s2]; redarg[tid] += redarg[tid + s2]; }
            __syncthreads();
        }
        if (tid == 0) {
            const float inv = 1.0f / (float)(BB * NQ);
            float loss = redmin[0] * inv;
            float accu = (float)redarg[0] * inv;
            if (out_size >= BB * NQ + 2) {
                out[BB * NQ] = loss;
                out[BB * NQ + 1] = accu;
            } else if (out_size == 2) {
                out[0] = loss; out[1] = accu;
            } else if (out_size == 1) {
                out[0] = loss;
            }
            g_done = 0;   // self-reset for graph replays
        }
    }
}

// ---------------------------------------------------------------------------
extern "C" void kernel_launch(void* const* d_in, const int* in_sizes, int n_in,
                              void* d_out, int out_size) {
    const float* sup  = (const float*)d_in[0];
    const float* qry  = (const float*)d_in[1];
    const int*   stgt = (const int*)d_in[2];
    const int*   qtgt = (const int*)d_in[3];
    float* out = (float*)d_out;

    cudaFuncSetAttribute(gemm_kernel,
                         cudaFuncAttributeMaxDynamicSharedMemorySize, SMEM_GEMM);

    psum_kernel<<<dim3(CC, BB), 256>>>(sup, stgt);

    float* pred_out = (out_size >= BB * NQ) ? out : nullptr;
    gemm_kernel<<<dim3(NQ / QTILE, BB), 256, SMEM_GEMM>>>(qry, qtgt, pred_out,
                                                          out, out_size);
}

// round 17
// speedup vs baseline: 1.4368x; 1.4368x over previous
#include <cuda_runtime.h>
#include <cuda_fp16.h>
#include <math.h>
#include <float.h>
#include <stdint.h>

#define BB 16
#define NS 4096
#define NQ 4096
#define DD 512
#define CC 128
#define QTILE 64
#define GEMM_BLOCKS (BB * (NQ / QTILE))   // 1024
#define MARGIN 0.25f

// ---------------- static device scratch (no runtime alloc) ----------------
__device__ __half g_proto_h[(size_t)BB * CC * DD];            // [b][c][d] fp16
__device__ float  g_proto_f[(size_t)BB * CC * DD];            // [b][c][d] fp32
__device__ float  g_psq[BB * CC];
__device__ float  g_loss_part[GEMM_BLOCKS];
__device__ int    g_corr_part[GEMM_BLOCKS];

// ---------------- helpers ----------------
__device__ __forceinline__ uint32_t smem_u32(const void* p) {
    uint32_t a;
    asm("{ .reg .u64 t; cvta.to.shared.u64 t, %1; cvt.u32.u64 %0, t; }" : "=r"(a) : "l"(p));
    return a;
}
__device__ __forceinline__ void cp_async16(uint32_t dst, const void* src) {
    asm volatile("cp.async.cg.shared.global [%0], [%1], 16;" :: "r"(dst), "l"(src));
}
__device__ __forceinline__ void cp_commit() {
    asm volatile("cp.async.commit_group;" ::: "memory");
}
__device__ __forceinline__ void cp_wait0() {
    asm volatile("cp.async.wait_group 0;" ::: "memory");
}
__device__ __forceinline__ void ldsm4(uint32_t* r, uint32_t addr) {
    asm volatile("ldmatrix.sync.aligned.m8n8.x4.shared.b16 {%0,%1,%2,%3}, [%4];"
                 : "=r"(r[0]), "=r"(r[1]), "=r"(r[2]), "=r"(r[3]) : "r"(addr));
}
__device__ __forceinline__ void mma_f16(float* c, const uint32_t* a,
                                        uint32_t b0, uint32_t b1) {
    asm volatile("mma.sync.aligned.m16n8k16.row.col.f32.f16.f16.f32 "
                 "{%0,%1,%2,%3}, {%4,%5,%6,%7}, {%8,%9}, {%0,%1,%2,%3};"
                 : "+f"(c[0]), "+f"(c[1]), "+f"(c[2]), "+f"(c[3])
                 : "r"(a[0]), "r"(a[1]), "r"(a[2]), "r"(a[3]), "r"(b0), "r"(b1));
}
__device__ __forceinline__ uint32_t pkhf(float a, float b) {
    __half2 t = __floats2half2_rn(a, b);
    return *reinterpret_cast<uint32_t*>(&t);
}

// ---------------------------------------------------------------------------
// Kernel 1: fused stable-compaction + gather-sum prototypes (R15 version).
// Grid (128 c, 16 b), 512 threads (thread = d-lane; handles 8 targets).
// ---------------------------------------------------------------------------
__global__ void psum_kernel(const float* __restrict__ sup,
                            const int* __restrict__ stgt) {
    __shared__ int   sidx[NS];        // 16 KB
    __shared__ int   scanbuf[512];
    __shared__ float red[512];
    const int c = blockIdx.x, b = blockIdx.y, d = threadIdx.x;

    // ---- Phase A: stable compaction of sample ids matching class c ----
    int t8[8];
    {
        const int* tg = stgt + (size_t)b * NS + d * 8;
        *(int4*)(t8)     = *(const int4*)(tg);
        *(int4*)(t8 + 4) = *(const int4*)(tg + 4);
    }
    int cnt = 0;
    #pragma unroll
    for (int u = 0; u < 8; u++) cnt += (t8[u] == c);
    scanbuf[d] = cnt;
    __syncthreads();
    for (int off = 1; off < 512; off <<= 1) {
        int v = (d >= off) ? scanbuf[d - off] : 0;
        __syncthreads();
        scanbuf[d] += v;
        __syncthreads();
    }
    int w = scanbuf[d] - cnt;
    const int total = scanbuf[511];
    #pragma unroll
    for (int u = 0; u < 8; u++)
        if (t8[u] == c) sidx[w++] = d * 8 + u;
    __syncthreads();

    // ---- Phase B: gather-sum (8 independent chains for MLP) ----
    const float* supb = sup + (size_t)b * NS * DD + d;
    float s0 = 0.f, s1 = 0.f, s2 = 0.f, s3 = 0.f, s4 = 0.f, s5 = 0.f, s6 = 0.f, s7 = 0.f;
    int kk = 0;
    for (; kk + 8 <= total; kk += 8) {
        s0 += supb[(size_t)sidx[kk + 0] * DD];
        s1 += supb[(size_t)sidx[kk + 1] * DD];
        s2 += supb[(size_t)sidx[kk + 2] * DD];
        s3 += supb[(size_t)sidx[kk + 3] * DD];
        s4 += supb[(size_t)sidx[kk + 4] * DD];
        s5 += supb[(size_t)sidx[kk + 5] * DD];
        s6 += supb[(size_t)sidx[kk + 6] * DD];
        s7 += supb[(size_t)sidx[kk + 7] * DD];
    }
    for (; kk < total; kk++) s0 += supb[(size_t)sidx[kk] * DD];

    const float mean = (((s0 + s1) + (s2 + s3)) + ((s4 + s5) + (s6 + s7)))
                       / fmaxf((float)total, 1.0f);
    const size_t o = ((size_t)b * CC + c) * DD + d;
    g_proto_f[o] = mean;
    g_proto_h[o] = __float2half_rn(mean);

    red[d] = mean * mean;
    __syncthreads();
    for (int st = 256; st > 0; st >>= 1) {
        if (d < st) red[d] += red[d + st];
        __syncthreads();
    }
    if (d == 0) g_psq[b * CC + c] = red[0];
}

// ---------------------------------------------------------------------------
// Kernel 2: single-pass fp16 mma.sync distance GEMM (128c x 64q tiles),
// pipelined staging, fused argmin / per-query warp refinement / softmax-CE.
// Grid (64 qtiles, 16 b), 256 threads, 3 CTA/SM. NO fences (L1-flush trap).
// ---------------------------------------------------------------------------
#define OFF_RMIN  33792
#define OFF_RARG  34816
#define OFF_RSUM  35840
#define OFF_GMIN  36864
#define OFF_GARG  37120
#define SMEM_GEMM 49152

__global__ __launch_bounds__(256, 3)
void gemm_kernel(const float* __restrict__ qry,
                 const int* __restrict__ qtgt,
                 float* __restrict__ pred_out) {
    extern __shared__ char smem[];
    const uint32_t smb = smem_u32(smem);
    float* dist   = (float*)smem;                 // [128 c][66]
    float* redmin = (float*)(smem + OFF_RMIN);    // [4][64]
    int*   redarg = (int*)  (smem + OFF_RARG);
    float* redsum = (float*)(smem + OFF_RSUM);
    float* gmin   = (float*)(smem + OFF_GMIN);    // [64]
    int*   garg   = (int*)  (smem + OFF_GARG);

    const int tid = threadIdx.x, wid = tid >> 5, lane = tid & 31;
    const int mw = wid & 3, nw = wid >> 2;
    const int qt = blockIdx.x, b = blockIdx.y, q0 = qt * QTILE;

    const float* Qb = qry + ((size_t)b * NQ + q0) * DD;
    const __half* Ah = g_proto_h + (size_t)b * CC * DD;

    float acc[2][4][4];
    #pragma unroll
    for (int i = 0; i < 2; i++)
        #pragma unroll
        for (int j = 0; j < 4; j++)
            #pragma unroll
            for (int k = 0; k < 4; k++) acc[i][j][k] = 0.0f;

    const uint32_t rowTerm = (uint32_t)(lane & 15) << 7;
    const uint32_t sel16   = (uint32_t)(lane & 16);
    const uint32_t laneXor = (uint32_t)(lane & 7) << 4;

    // ---- prologue: stage chunk 0 into buffer 0 ----
    {
        #pragma unroll
        for (int p = 0; p < 4; p++) {
            int idx = p * 256 + tid;
            int row = idx >> 3, c16 = idx & 7;
            uint32_t sw = (uint32_t)(row * 128 + c16 * 16) ^ ((uint32_t)(row & 7) << 4);
            cp_async16(smb + 0 + sw, Ah + (size_t)row * DD + c16 * 8);
        }
        cp_commit();
        #pragma unroll
        for (int p = 0; p < 2; p++) {
            int idx = p * 256 + tid;
            int row = idx >> 3, c16 = idx & 7;
            const float* src = Qb + (size_t)row * DD + c16 * 8;
            float4 v0 = *(const float4*)(src);
            float4 v1 = *(const float4*)(src + 4);
            uint32_t sw = (uint32_t)(row * 128 + c16 * 16) ^ ((uint32_t)(row & 7) << 4);
            *(uint4*)(smem + 32768 + sw) =
                make_uint4(pkhf(v0.x, v0.y), pkhf(v0.z, v0.w), pkhf(v1.x, v1.y), pkhf(v1.z, v1.w));
        }
        cp_wait0();
        __syncthreads();
    }

    for (int ck = 0; ck < 8; ck++) {
        const int cur = ck & 1;
        float4 bv0[2], bv1[2];
        if (ck < 7) {
            const int k0 = (ck + 1) * 64;
            const uint32_t aBuf = (cur ^ 1) * 16384u;
            #pragma unroll
            for (int p = 0; p < 4; p++) {
                int idx = p * 256 + tid;
                int row = idx >> 3, c16 = idx & 7;
                uint32_t sw = (uint32_t)(row * 128 + c16 * 16) ^ ((uint32_t)(row & 7) << 4);
                cp_async16(smb + aBuf + sw, Ah + (size_t)row * DD + k0 + c16 * 8);
            }
            cp_commit();
            #pragma unroll
            for (int p = 0; p < 2; p++) {
                int idx = p * 256 + tid;
                int row = idx >> 3, c16 = idx & 7;
                const float* src = Qb + (size_t)row * DD + k0 + c16 * 8;
                bv0[p] = *(const float4*)(src);
                bv1[p] = *(const float4*)(src + 4);
            }
        }

        // ---- compute current buffer ----
        {
            const uint32_t aT = smb + cur * 16384u;
            const uint32_t bT = smb + 32768u + cur * 8192u;
            #pragma unroll
            for (int ks = 0; ks < 4; ks++) {
                const uint32_t kb = ((uint32_t)(ks * 32) | sel16) ^ laneXor;
                uint32_t afr[2][4], bfr[2][4];
                #pragma unroll
                for (int mt = 0; mt < 2; mt++)
                    ldsm4(afr[mt], aT + ((uint32_t)(mw * 32 + mt * 16) << 7) + rowTerm + kb);
                #pragma unroll
                for (int g = 0; g < 2; g++)
                    ldsm4(bfr[g], bT + ((uint32_t)(nw * 32 + g * 16) << 7) + rowTerm + kb);
                #pragma unroll
                for (int mt = 0; mt < 2; mt++)
                    #pragma unroll
                    for (int g = 0; g < 2; g++) {
                        mma_f16(acc[mt][2 * g + 0], afr[mt], bfr[g][0], bfr[g][2]);
                        mma_f16(acc[mt][2 * g + 1], afr[mt], bfr[g][1], bfr[g][3]);
                    }
            }
        }

        if (ck < 7) {
            const uint32_t bBuf = 32768u + (cur ^ 1) * 8192u;
            #pragma unroll
            for (int p = 0; p < 2; p++) {
                int idx = p * 256 + tid;
                int row = idx >> 3, c16 = idx & 7;
                uint32_t sw = (uint32_t)(row * 128 + c16 * 16) ^ ((uint32_t)(row & 7) << 4);
                *(uint4*)(smem + bBuf + sw) =
                    make_uint4(pkhf(bv0[p].x, bv0[p].y), pkhf(bv0[p].z, bv0[p].w),
                               pkhf(bv1[p].x, bv1[p].y), pkhf(bv1[p].z, bv1[p].w));
            }
            cp_wait0();
        }
        __syncthreads();
    }

    // ---- dist = p_sq - 2*cross (q_sq cancels) ----
    #pragma unroll
    for (int mt = 0; mt < 2; mt++) {
        int cA = mw * 32 + mt * 16 + (lane >> 2);
        float psA = g_psq[b * CC + cA];
        float psB = g_psq[b * CC + cA + 8];
        #pragma unroll
        for (int nt = 0; nt < 4; nt++) {
            int q = nw * 32 + nt * 8 + 2 * (lane & 3);
            float* d0 = &dist[cA * 66 + q];
            float* d1 = &dist[(cA + 8) * 66 + q];
            d0[0] = psA - 2.0f * acc[mt][nt][0];
            d0[1] = psA - 2.0f * acc[mt][nt][1];
            d1[0] = psB - 2.0f * acc[mt][nt][2];
            d1[1] = psB - 2.0f * acc[mt][nt][3];
        }
    }
    __syncthreads();

    // ---- pass 1: per-quarter min -> global approx min ----
    const int q = tid & 63, qr = tid >> 6, c0 = qr * 32;
    {
        float mn = FLT_MAX; int am = 0;
        #pragma unroll 8
        for (int c = 0; c < 32; c++) {
            float v = dist[(c0 + c) * 66 + q];
            if (v < mn) { mn = v; am = c0 + c; }
        }
        redmin[qr * 64 + q] = mn;
        redarg[qr * 64 + q] = am;
    }
    __syncthreads();
    if (tid < QTILE) {
        float g = FLT_MAX; int ga = 0;
        #pragma unroll
        for (int i = 0; i < 4; i++) {
            float v = redmin[i * 64 + tid];
            if (v < g) { g = v; ga = redarg[i * 64 + tid]; }
        }
        gmin[tid] = g; garg[tid] = ga;
    }
    __syncthreads();

    // ---- per-query warp refinement (ballot-scan, no lists/atomics) ----
    for (int qq = wid; qq < QTILE; qq += 8) {
        const float gthr = gmin[qq] + MARGIN;
        uint32_t masks[4]; int cnt = 0;
        #pragma unroll
        for (int k = 0; k < 4; k++) {
            bool cand = dist[(k * 32 + lane) * 66 + qq] < gthr;
            masks[k] = __ballot_sync(0xFFFFFFFFu, cand);
            cnt += __popc(masks[k]);
        }
        if (cnt < 2) continue;
        float4 qv[4];
        const float4* Q4 = (const float4*)(Qb + (size_t)qq * DD);
        #pragma unroll
        for (int j = 0; j < 4; j++) qv[j] = Q4[lane + j * 32];
        #pragma unroll
        for (int k = 0; k < 4; k++) {
            uint32_t m = masks[k];
            while (m) {
                int c = k * 32 + (__ffs(m) - 1);
                m &= m - 1;
                const float4* P = (const float4*)(g_proto_f + ((size_t)b * CC + c) * DD);
                float s = 0.0f;
                #pragma unroll
                for (int j = 0; j < 4; j++) {
                    float4 a = P[lane + j * 32];
                    s = fmaf(a.x, qv[j].x, s);
                    s = fmaf(a.y, qv[j].y, s);
                    s = fmaf(a.z, qv[j].z, s);
                    s = fmaf(a.w, qv[j].w, s);
                }
                #pragma unroll
                for (int o = 16; o > 0; o >>= 1)
                    s += __shfl_xor_sync(0xFFFFFFFFu, s, o);
                if (lane == 0)
                    dist[c * 66 + qq] = g_psq[b * CC + c] - 2.0f * s;
            }
        }
    }
    __syncthreads();

    // ---- final argmin on refined dist ----
    {
        float mn = FLT_MAX; int am = 0;
        #pragma unroll 8
        for (int c = 0; c < 32; c++) {
            float v = dist[(c0 + c) * 66 + q];
            if (v < mn) { mn = v; am = c0 + c; }
        }
        redmin[qr * 64 + q] = mn;
        redarg[qr * 64 + q] = am;
    }
    __syncthreads();
    if (tid < QTILE) {
        float g = FLT_MAX; int ga = 0;
        #pragma unroll
        for (int i = 0; i < 4; i++) {
            float v = redmin[i * 64 + tid];
            if (v < g) { g = v; ga = redarg[i * 64 + tid]; }
        }
        gmin[tid] = g; garg[tid] = ga;
    }
    __syncthreads();

    // ---- softmax-CE: __expf intrinsic ----
    {
        float g = gmin[q];
        float s = 0.0f;
        #pragma unroll 8
        for (int c = 0; c < 32; c++)
            s += __expf(g - dist[(c0 + c) * 66 + q]);
        redsum[qr * 64 + q] = s;
    }
    __syncthreads();

    if (tid < QTILE) {
        float S = redsum[tid] + redsum[64 + tid] + redsum[128 + tid] + redsum[192 + tid];
        int tgt = qtgt[(size_t)b * NQ + q0 + tid];
        float tl = dist[tgt * 66 + tid];
        float nll = tl - gmin[tid] + logf(S);
        int corr = (garg[tid] == tgt);
        if (pred_out) pred_out[(size_t)b * NQ + q0 + tid] = (float)garg[tid];
        redmin[tid] = nll;
        redarg[tid] = corr;
    }
    __syncthreads();
    for (int s2 = 32; s2 > 0; s2 >>= 1) {
        if (tid < s2) { redmin[tid] += redmin[tid + s2]; redarg[tid] += redarg[tid + s2]; }
        __syncthreads();
    }
    if (tid == 0) {
        g_loss_part[b * (NQ / QTILE) + qt] = redmin[0];
        g_corr_part[b * (NQ / QTILE) + qt] = redarg[0];
    }
}

// ---------------------------------------------------------------------------
// Kernel 3: deterministic final reduction + tail writes. 1024 threads.
// ---------------------------------------------------------------------------
__global__ void finalize_kernel(float* __restrict__ out, int out_size) {
    __shared__ float sl[GEMM_BLOCKS];
    __shared__ int   sc[GEMM_BLOCKS];
    int t = threadIdx.x;
    sl[t] = g_loss_part[t];
    sc[t] = g_corr_part[t];
    __syncthreads();
    for (int s = GEMM_BLOCKS / 2; s > 0; s >>= 1) {
        if (t < s) { sl[t] += sl[t + s]; sc[t] += sc[t + s]; }
        __syncthreads();
    }
    if (t == 0) {
        const float inv = 1.0f / (float)(BB * NQ);
        float loss = sl[0] * inv;
        float accu = (float)sc[0] * inv;
        if (out_size >= BB * NQ + 2) {
            out[BB * NQ] = loss;
            out[BB * NQ + 1] = accu;
        } else if (out_size == 2) {
            out[0] = loss; out[1] = accu;
        } else if (out_size == 1) {
            out[0] = loss;
        }
    }
}

// ---------------------------------------------------------------------------
extern "C" void kernel_launch(void* const* d_in, const int* in_sizes, int n_in,
                              void* d_out, int out_size) {
    const float* sup  = (const float*)d_in[0];
    const float* qry  = (const float*)d_in[1];
    const int*   stgt = (const int*)d_in[2];
    const int*   qtgt = (const int*)d_in[3];
    float* out = (float*)d_out;

    cudaFuncSetAttribute(gemm_kernel,
                         cudaFuncAttributeMaxDynamicSharedMemorySize, SMEM_GEMM);

    psum_kernel<<<dim3(CC, BB), 512>>>(sup, stgt);

    float* pred_out = (out_size >= BB * NQ) ? out : nullptr;
    gemm_kernel<<<dim3(NQ / QTILE, BB), 256, SMEM_GEMM>>>(qry, qtgt, pred_out);

    finalize_kernel<<<1, GEMM_BLOCKS>>>(out, out_size);
}